// round 3
// baseline (speedup 1.0000x reference)
#include <cuda_runtime.h>
#include <cuda_bf16.h>
#include <cstdint>
#include <cstddef>

// y[32,11008] = x[32,4096] @ (Wq * scale)^T + bias
// Base-ISA (target sm_103): mma.sync m16n8k16 bf16 + cp.async 5-stage W pipeline.
// Ternary W -> bf16 exact; x -> hi/lo bf16 split (err ~2^-17).
// sigma K-permutation keeps all fragment loads contiguous.

#define OUTN 11008
#define INK  4096
#define TM   128
#define KC   64
#define NCHUNK (INK / KC)   // 64
#define NCTA (OUTN / TM)    // 86
#define NTHREADS 256
#define XROW 160            // x smem row stride (bytes)
#define WROW 272            // W smem row stride (bytes): 256 data + 16 pad
#define WSTAGE (128 * WROW) // 34816 B per stage
#define STAGES 5
#define XTILE (64 * XROW)   // 10240 B
#define SMEM_X0 (STAGES * WSTAGE)
#define SMEM_X1 (SMEM_X0 + XTILE)
#define SMEM_TOTAL (SMEM_X1 + XTILE)   // 194560 B

__device__ __forceinline__ uint32_t pack_bf(int x, int y) {
    __nv_bfloat162 p = __floats2bfloat162_rn((float)x, (float)y);
    return *reinterpret_cast<uint32_t*>(&p);
}

__device__ __forceinline__ void mma16816(float d[4],
                                         uint32_t a0, uint32_t a1, uint32_t a2, uint32_t a3,
                                         uint32_t b0, uint32_t b1) {
    asm volatile(
        "mma.sync.aligned.m16n8k16.row.col.f32.bf16.bf16.f32 "
        "{%0,%1,%2,%3}, {%4,%5,%6,%7}, {%8,%9}, {%0,%1,%2,%3};\n"
        : "+f"(d[0]), "+f"(d[1]), "+f"(d[2]), "+f"(d[3])
        : "r"(a0), "r"(a1), "r"(a2), "r"(a3), "r"(b0), "r"(b1));
}

__device__ __forceinline__ void cp16(uint32_t dst, const void* src) {
    asm volatile("cp.async.cg.shared.global [%0], [%1], 16;\n"
                 :: "r"(dst), "l"(src));
}
__device__ __forceinline__ void cp_commit() {
    asm volatile("cp.async.commit_group;\n" ::: "memory");
}
__device__ __forceinline__ void cp_wait3() {
    asm volatile("cp.async.wait_group 3;\n" ::: "memory");
}

struct XV { float4 a, b; };

__device__ __forceinline__ XV load_x(const float* __restrict__ X, int tid, int ch) {
    XV v;
    int f0 = tid, f1 = tid + NTHREADS;
    v.a = *reinterpret_cast<const float4*>(X + (size_t)(f0 >> 4) * INK + ch * KC + (f0 & 15) * 4);
    v.b = *reinterpret_cast<const float4*>(X + (size_t)(f1 >> 4) * INK + ch * KC + (f1 & 15) * 4);
    return v;
}

__device__ __forceinline__ void cvt_store_one(float4 u, int f, unsigned char* xb) {
    int b  = f >> 4;
    int k4 = (f & 15) * 4;
    __nv_bfloat16 h0 = __float2bfloat16_rn(u.x);
    __nv_bfloat16 h1 = __float2bfloat16_rn(u.y);
    __nv_bfloat16 h2 = __float2bfloat16_rn(u.z);
    __nv_bfloat16 h3 = __float2bfloat16_rn(u.w);
    __nv_bfloat16 l0 = __float2bfloat16_rn(u.x - __bfloat162float(h0));
    __nv_bfloat16 l1 = __float2bfloat16_rn(u.y - __bfloat162float(h1));
    __nv_bfloat16 l2 = __float2bfloat16_rn(u.z - __bfloat162float(h2));
    __nv_bfloat16 l3 = __float2bfloat16_rn(u.w - __bfloat162float(h3));
    __nv_bfloat162 hp0; hp0.x = h0; hp0.y = h1;
    __nv_bfloat162 hp1; hp1.x = h2; hp1.y = h3;
    __nv_bfloat162 lp0; lp0.x = l0; lp0.y = l1;
    __nv_bfloat162 lp1; lp1.x = l2; lp1.y = l3;
    uint2 hv = make_uint2(*reinterpret_cast<uint32_t*>(&hp0), *reinterpret_cast<uint32_t*>(&hp1));
    uint2 lv = make_uint2(*reinterpret_cast<uint32_t*>(&lp0), *reinterpret_cast<uint32_t*>(&lp1));
    *reinterpret_cast<uint2*>(xb + b * XROW + k4 * 2) = hv;
    *reinterpret_cast<uint2*>(xb + (b + 32) * XROW + k4 * 2) = lv;
}

__device__ __forceinline__ void store_x(XV v, unsigned char* xb, int tid) {
    cvt_store_one(v.a, tid, xb);
    cvt_store_one(v.b, tid + NTHREADS, xb);
}

// W cp.async issue for one chunk into one stage.
// thread role: tr = tid>>4 (0..15), c16 = tid&15; 8 iters cover 128 rows.
__device__ __forceinline__ void issue_w(const char* srcbase, uint32_t dstbase, int ch) {
#pragma unroll
    for (int j = 0; j < 8; ++j) {
        cp16(dstbase + j * (16 * WROW),
             srcbase + (size_t)j * 16 * INK * 4 + (size_t)ch * 256);
    }
}

__device__ __forceinline__ void compute(const unsigned char* wsm, const unsigned char* xb,
                                        int wid, int lane, float acc[8][4]) {
    int rr = lane >> 2;
    int cc = lane & 3;
    const unsigned char* wr0 = wsm + (wid * 16 + rr) * WROW + cc * 16;
#pragma unroll
    for (int s = 0; s < 4; ++s) {
        int4 wa = *reinterpret_cast<const int4*>(wr0 + s * 64);
        int4 wb = *reinterpret_cast<const int4*>(wr0 + 8 * WROW + s * 64);
        uint32_t a0 = pack_bf(wa.x, wa.y);
        uint32_t a2 = pack_bf(wa.z, wa.w);
        uint32_t a1 = pack_bf(wb.x, wb.y);
        uint32_t a3 = pack_bf(wb.z, wb.w);
#pragma unroll
        for (int nf = 0; nf < 8; ++nf) {
            uint2 bv = *reinterpret_cast<const uint2*>(
                xb + (nf * 8 + rr) * XROW + s * 32 + cc * 8);
            mma16816(acc[nf], a0, a1, a2, a3, bv.x, bv.y);
        }
    }
}

__global__ void __launch_bounds__(NTHREADS)
lin2b_kernel(const float* __restrict__ X, const int* __restrict__ W,
             const float* __restrict__ SC, const float* __restrict__ BI,
             float* __restrict__ OUT)
{
    extern __shared__ __align__(16) unsigned char smem[];
    unsigned char* xsm[2] = { smem + SMEM_X0, smem + SMEM_X1 };

    int tid  = threadIdx.x;
    int wid  = tid >> 5;
    int lane = tid & 31;
    int rr   = lane >> 2;
    int cc   = lane & 3;
    int row0 = blockIdx.x * TM;

    // cp.async thread mapping
    int tr  = tid >> 4;          // 0..15
    int c16 = tid & 15;          // 0..15
    const char* wsrc = reinterpret_cast<const char*>(
        W + (size_t)(row0 + tr) * INK + c16 * 4);
    uint32_t smem_u = (uint32_t)__cvta_generic_to_shared(smem);
    uint32_t wdst_t = smem_u + tr * WROW + c16 * 16;

    float acc[8][4];
#pragma unroll
    for (int i = 0; i < 8; ++i)
#pragma unroll
        for (int j = 0; j < 4; ++j) acc[i][j] = 0.0f;

    // ---- prologue: issue W chunks 0..3, stage x chunk 0 ----
#pragma unroll
    for (int p = 0; p < STAGES - 1; ++p) {
        issue_w(wsrc, wdst_t + p * WSTAGE, p);
        cp_commit();
    }
    {
        XV v = load_x(X, tid, 0);
        store_x(v, xsm[0], tid);
    }

    // ---- main loop ----
#pragma unroll 1
    for (int c = 0; c < NCHUNK; ++c) {
        XV v;
        bool morex = (c + 1) < NCHUNK;
        if (morex) v = load_x(X, tid, c + 1);

        cp_wait3();          // W chunk c resident (this thread's groups)
        __syncthreads();     // all threads' chunk-c data + x buf visible

        // reissue into the stage consumed at iter c-1 (all warps past it now)
        int cn = c + STAGES - 1;
        if (cn < NCHUNK) issue_w(wsrc, wdst_t + (cn % STAGES) * WSTAGE, cn);
        cp_commit();         // dummy group in tail keeps wait_group 3 exact

        compute(smem + (c % STAGES) * WSTAGE, xsm[c & 1], wid, lane, acc);
        if (morex) store_x(v, xsm[(c + 1) & 1], tid);
    }

    // ---- epilogue: acc[nf] (hi) + acc[nf+4] (lo), scale + bias ----
    int o0 = row0 + wid * 16 + rr;
    int o1 = o0 + 8;
    float s0 = SC[o0], bi0 = BI[o0];
    float s1 = SC[o1], bi1 = BI[o1];
#pragma unroll
    for (int nf = 0; nf < 4; ++nf) {
        int b0 = nf * 8 + 2 * cc;
        int b1 = b0 + 1;
        float v00 = acc[nf][0] + acc[nf + 4][0];
        float v01 = acc[nf][1] + acc[nf + 4][1];
        float v10 = acc[nf][2] + acc[nf + 4][2];
        float v11 = acc[nf][3] + acc[nf + 4][3];
        OUT[(size_t)b0 * OUTN + o0] = fmaf(s0, v00, bi0);
        OUT[(size_t)b1 * OUTN + o0] = fmaf(s0, v01, bi0);
        OUT[(size_t)b0 * OUTN + o1] = fmaf(s1, v10, bi1);
        OUT[(size_t)b1 * OUTN + o1] = fmaf(s1, v11, bi1);
    }
}

extern "C" void kernel_launch(void* const* d_in, const int* in_sizes, int n_in,
                              void* d_out, int out_size) {
    (void)in_sizes; (void)n_in; (void)out_size;
    const float* x  = (const float*)d_in[0];
    const int*   wq = (const int*)d_in[1];
    const float* sc = (const float*)d_in[2];
    const float* bi = (const float*)d_in[3];
    float* out = (float*)d_out;

    cudaFuncSetAttribute(lin2b_kernel,
                         cudaFuncAttributeMaxDynamicSharedMemorySize, SMEM_TOTAL);
    lin2b_kernel<<<NCTA, NTHREADS, SMEM_TOTAL>>>(x, wq, sc, bi, out);
}